// round 6
// baseline (speedup 1.0000x reference)
#include <cuda_runtime.h>
#include <math.h>

#define TT   128      // timesteps
#define BB   128      // batch
#define EMBD 300
#define UU   512
#define GG   2048     // 4*U
#define TBROWS (TT*BB)
#define NBLK 128      // persistent blocks (<=148 SMs -> single wave, spin barrier safe)

typedef unsigned long long u64;

// packed fp32x2 helpers (sm_103a FFMA2 — only reachable via PTX)
__device__ __forceinline__ u64 pack2(float lo, float hi) {
    u64 r; asm("mov.b64 %0, {%1, %2};" : "=l"(r) : "f"(lo), "f"(hi)); return r;
}
__device__ __forceinline__ float2 unpack2(u64 v) {
    float2 f; asm("mov.b64 {%0, %1}, %2;" : "=f"(f.x), "=f"(f.y) : "l"(v)); return f;
}
__device__ __forceinline__ u64 fma2(u64 a, u64 b, u64 c) {
    u64 d; asm("fma.rn.f32x2 %0, %1, %2, %3;" : "=l"(d) : "l"(a), "l"(b), "l"(c)); return d;
}

// ---------------- scratch (static device arrays; no allocation) -------------
static __device__ float g_X[TBROWS*EMBD];                 // [t][b][e]
static __device__ float g_Zpre[2][TBROWS*GG];             // per dir: x@W + b for all (t,b)
static __device__ float g_Hseq[2][2][TBROWS*UU];          // [dir][ping][(s*B+r)*U + col]
static __device__ float g_HT[2][2][UU*BB];                // [dir][parity][col*BB + row]
static __device__ float g_mid[BB*(UU/2)];                 // dense0 output

// barrier state (zero-init; reset at end of each persistent kernel)
static __device__ unsigned g_bar_cnt = 0;
static __device__ unsigned g_bar_gen = 0;

__device__ __forceinline__ void grid_sync(unsigned target) {
    __syncthreads();
    if (threadIdx.x == 0) {
        __threadfence();
        unsigned old = atomicAdd(&g_bar_cnt, 1);
        if (old == NBLK - 1) {
            g_bar_cnt = 0;
            __threadfence();
            atomicAdd(&g_bar_gen, 1);
        } else {
            while (*(volatile unsigned*)&g_bar_gen < target) { }
        }
    }
    __syncthreads();
}

// ---------------- embedding gather ------------------------------------------
__global__ void embed_kernel(const int* __restrict__ ids, const float* __restrict__ emb) {
    int idx = blockIdx.x*256 + threadIdx.x;
    if (idx >= TBROWS*EMBD) return;
    int row = idx / EMBD;           // t*BB + b
    int e   = idx - row*EMBD;
    int t   = row >> 7;
    int b   = row & 127;
    g_X[idx] = emb[(size_t)ids[b*TT + t]*EMBD + e];
}

// ---------------- input projection: Zpre = In @ W + bias --------------------
// BM=128, BN=128, BK=16, 256 threads, 8x8 per thread via packed f32x2 FMAs.
// grid: (GG/128, TBROWS/128, 2). B tile stored pre-broadcast-packed (w,w) u64.
__global__ void pregemm_kernel(const float* __restrict__ Wf, const float* __restrict__ bf,
                               const float* __restrict__ Wb, const float* __restrict__ bbv,
                               int layer)
{
    int d = blockIdx.z;
    const float* W    = d ? Wb  : Wf;
    const float* bias = d ? bbv : bf;
    const float* A    = (layer == 0) ? g_X : g_Hseq[d][(layer + 1) & 1];
    int K             = (layer == 0) ? EMBD : UU;
    float* Z = g_Zpre[d];

    int n0 = blockIdx.x * 128;
    int m0 = blockIdx.y * 128;
    int tid = threadIdx.x;
    int tx = tid & 15, ty = tid >> 4;     // tx: 8-col group, ty: 8-row group

    __shared__ float As[16][132];         // [k][row], padded
    __shared__ u64   Bs2[16][128];        // [k][n] broadcast-packed (w,w)

    u64 acc[4][8];                        // [row-pair][col]
    #pragma unroll
    for (int p = 0; p < 4; ++p)
        #pragma unroll
        for (int j = 0; j < 8; ++j) acc[p][j] = 0ull;

    int nch = (K + 15) >> 4;
    for (int ch = 0; ch < nch; ++ch) {
        int k0 = ch << 4;
        // A tile: 128 rows x 16 k (float4 per thread x2)
        #pragma unroll
        for (int h = 0; h < 2; ++h) {
            int e = tid + h*256;
            int row = e >> 2, kq = (e & 3) << 2;
            float4 v = make_float4(0.f, 0.f, 0.f, 0.f);
            if (k0 + kq < K) v = *(const float4*)&A[(size_t)(m0 + row)*K + k0 + kq];
            As[kq + 0][row] = v.x; As[kq + 1][row] = v.y;
            As[kq + 2][row] = v.z; As[kq + 3][row] = v.w;
        }
        // B tile: 16 k x 128 n, broadcast-packed
        #pragma unroll
        for (int h = 0; h < 2; ++h) {
            int e  = tid + h*256;         // 512 float4 total
            int kk = e >> 5;
            int nq = (e & 31) << 2;
            float4 v = make_float4(0.f, 0.f, 0.f, 0.f);
            if (k0 + kk < K) v = *(const float4*)&W[(size_t)(k0 + kk)*GG + n0 + nq];
            Bs2[kk][nq + 0] = pack2(v.x, v.x);
            Bs2[kk][nq + 1] = pack2(v.y, v.y);
            Bs2[kk][nq + 2] = pack2(v.z, v.z);
            Bs2[kk][nq + 3] = pack2(v.w, v.w);
        }
        __syncthreads();
        #pragma unroll
        for (int kk = 0; kk < 16; ++kk) {
            // row pairs directly from shared (adjacent floats = packed pair)
            ulonglong2 a01 = *(const ulonglong2*)&As[kk][ty*8];
            ulonglong2 a23 = *(const ulonglong2*)&As[kk][ty*8 + 4];
            u64 ap[4] = {a01.x, a01.y, a23.x, a23.y};
            u64 bq[8];
            *(ulonglong2*)&bq[0] = *(const ulonglong2*)&Bs2[kk][tx*8 + 0];
            *(ulonglong2*)&bq[2] = *(const ulonglong2*)&Bs2[kk][tx*8 + 2];
            *(ulonglong2*)&bq[4] = *(const ulonglong2*)&Bs2[kk][tx*8 + 4];
            *(ulonglong2*)&bq[6] = *(const ulonglong2*)&Bs2[kk][tx*8 + 6];
            #pragma unroll
            for (int p = 0; p < 4; ++p)
                #pragma unroll
                for (int j = 0; j < 8; ++j)
                    acc[p][j] = fma2(ap[p], bq[j], acc[p][j]);
        }
        __syncthreads();
    }
    // epilogue: unpack pairs, add bias, store 8 rows x 8 cols
    int n = n0 + tx*8;
    float bl[8];
    #pragma unroll
    for (int j = 0; j < 8; ++j) bl[j] = bias[n + j];
    #pragma unroll
    for (int p = 0; p < 4; ++p) {
        int m = m0 + ty*8 + 2*p;
        float r0v[8], r1v[8];
        #pragma unroll
        for (int j = 0; j < 8; ++j) {
            float2 f = unpack2(acc[p][j]);
            r0v[j] = f.x + bl[j];
            r1v[j] = f.y + bl[j];
        }
        *(float4*)&Z[(size_t)m*GG + n]         = make_float4(r0v[0], r0v[1], r0v[2], r0v[3]);
        *(float4*)&Z[(size_t)m*GG + n + 4]     = make_float4(r0v[4], r0v[5], r0v[6], r0v[7]);
        *(float4*)&Z[(size_t)(m+1)*GG + n]     = make_float4(r1v[0], r1v[1], r1v[2], r1v[3]);
        *(float4*)&Z[(size_t)(m+1)*GG + n + 4] = make_float4(r1v[4], r1v[5], r1v[6], r1v[7]);
    }
}

// ---------------- persistent recurrent layer kernel -------------------------
// 128 blocks x 128 threads. Block: dir = bid>>6, 8 h-cols (c0 = (bid&63)*8).
// U slice resident in smem as float4{i,f,g,o} per (k, hcol). Cell state in regs.
// Inner product uses packed f32x2 FMAs (row pairs packed from shared H chunk).
__global__ void lstm_layer_kernel(const float* __restrict__ Uf,
                                  const float* __restrict__ Ub, int layer)
{
    extern __shared__ char smem[];
    float4* Usv = (float4*)smem;              // [512][8] : k*8 + hc
    float*  Hs  = (float*)(smem + 65536);     // [16][128] : kk*128 + r

    int d   = blockIdx.x >> 6;
    int blk = blockIdx.x & 63;
    int c0  = blk << 3;
    const float* Uw = d ? Ub : Uf;
    const float* Zp = g_Zpre[d];
    int ping = layer & 1;
    float* Hseq = g_Hseq[d][ping];

    int tid = threadIdx.x;
    int tx = tid & 7;        // h-col within block
    int ty = tid >> 3;       // row-group (8 rows each)
    int j  = c0 + tx;        // global h index
    int r0 = ty << 3;

    // load U slice once (resident for all 128 steps)
    #pragma unroll 4
    for (int q = 0; q < 32; ++q) {
        int e  = q*128 + tid;
        int k  = e >> 3, hc = e & 7;
        int col = c0 + hc;
        float4 v;
        v.x = Uw[(size_t)k*GG +          col];
        v.y = Uw[(size_t)k*GG +   UU  +  col];
        v.z = Uw[(size_t)k*GG + 2*UU  +  col];
        v.w = Uw[(size_t)k*GG + 3*UU  +  col];
        Usv[k*8 + hc] = v;
    }
    __syncthreads();

    float c_reg[8];
    #pragma unroll
    for (int i = 0; i < 8; ++i) c_reg[i] = 0.f;

    unsigned bar = 0;
    for (int s = 0; s < TT; ++s) {
        // prefetch this step's Zpre rows (independent of H -> latency hides under matmul)
        int zr0 = (layer == 0 && d == 1) ? (TT - 1 - s) : s;
        float z0[8], z1[8], z2[8], z3[8];
        #pragma unroll
        for (int i = 0; i < 8; ++i) {
            const float* zp = Zp + ((size_t)zr0*BB + r0 + i)*GG + j;
            z0[i] = zp[0]; z1[i] = zp[UU]; z2[i] = zp[2*UU]; z3[i] = zp[3*UU];
        }

        u64 ac0[4], ac1[4], ac2[4], ac3[4];   // [row-pair] per gate
        #pragma unroll
        for (int p = 0; p < 4; ++p) { ac0[p] = 0ull; ac1[p] = 0ull; ac2[p] = 0ull; ac3[p] = 0ull; }

        if (s > 0) {
            const float4* HT = (const float4*)(g_HT[d][(s - 1) & 1]);
            float4 pf[4];
            #pragma unroll
            for (int q = 0; q < 4; ++q) pf[q] = __ldcg(HT + q*128 + tid);
            for (int ch = 0; ch < 32; ++ch) {
                #pragma unroll
                for (int q = 0; q < 4; ++q) ((float4*)Hs)[q*128 + tid] = pf[q];
                __syncthreads();
                if (ch < 31) {
                    const float4* src = HT + (ch + 1)*512;
                    #pragma unroll
                    for (int q = 0; q < 4; ++q) pf[q] = __ldcg(src + q*128 + tid);
                }
                #pragma unroll
                for (int kk = 0; kk < 16; ++kk) {
                    float4 u = Usv[(ch*16 + kk)*8 + tx];
                    u64 ux = pack2(u.x, u.x), uy = pack2(u.y, u.y);
                    u64 uz = pack2(u.z, u.z), uw = pack2(u.w, u.w);
                    ulonglong2 a01 = *(const ulonglong2*)&Hs[kk*128 + r0];
                    ulonglong2 a23 = *(const ulonglong2*)&Hs[kk*128 + r0 + 4];
                    u64 ap[4] = {a01.x, a01.y, a23.x, a23.y};
                    #pragma unroll
                    for (int p = 0; p < 4; ++p) {
                        ac0[p] = fma2(ap[p], ux, ac0[p]);
                        ac1[p] = fma2(ap[p], uy, ac1[p]);
                        ac2[p] = fma2(ap[p], uz, ac2[p]);
                        ac3[p] = fma2(ap[p], uw, ac3[p]);
                    }
                }
                __syncthreads();
            }
        }

        // gates + state update (thread-local)
        float hn[8];
        #pragma unroll
        for (int p = 0; p < 4; ++p) {
            float2 f0 = unpack2(ac0[p]);
            float2 f1 = unpack2(ac1[p]);
            float2 f2 = unpack2(ac2[p]);
            float2 f3 = unpack2(ac3[p]);
            float a0v[2] = {f0.x, f0.y}, a1v[2] = {f1.x, f1.y};
            float a2v[2] = {f2.x, f2.y}, a3v[2] = {f3.x, f3.y};
            #pragma unroll
            for (int e = 0; e < 2; ++e) {
                int i = 2*p + e;
                float zi = a0v[e] + z0[i];
                float zf = a1v[e] + z1[i];
                float zg = a2v[e] + z2[i];
                float zo = a3v[e] + z3[i];
                float ig = 1.f/(1.f + expf(-zi));
                float fg = 1.f/(1.f + expf(-zf));
                float sg = zg/(1.f + fabsf(zg));
                float og = 1.f/(1.f + expf(-zo));
                float cn = fg*c_reg[i] + ig*sg;
                c_reg[i] = cn;
                hn[i] = og*(cn/(1.f + fabsf(cn)));
                Hseq[((size_t)s*BB + r0 + i)*UU + j] = hn[i];
            }
        }
        float* HTc = g_HT[d][s & 1];
        *(float4*)&HTc[j*BB + r0]     = make_float4(hn[0], hn[1], hn[2], hn[3]);
        *(float4*)&HTc[j*BB + r0 + 4] = make_float4(hn[4], hn[5], hn[6], hn[7]);

        grid_sync(++bar);
    }

    // reset barrier generation for the next persistent launch / graph replay
    if (blockIdx.x == 0 && tid == 0) g_bar_gen = 0;
}

// ---------------- head: dense0 + BN + PReLU ---------------------------------
__global__ void dense0_kernel(const float* __restrict__ d0W, const float* __restrict__ d0b,
                              const float* __restrict__ gam, const float* __restrict__ bet,
                              const float* __restrict__ mea, const float* __restrict__ var,
                              const float* __restrict__ alp)
{
    int r = blockIdx.x;
    int jj = threadIdx.x;
    __shared__ float addv[UU];
    const float* hf = &g_Hseq[0][0][((size_t)(TT - 1)*BB + r)*UU];   // layer 2 -> ping 0
    const float* hb = &g_Hseq[1][0][((size_t)(TT - 1)*BB + r)*UU];
    for (int k = jj; k < UU; k += 256) addv[k] = 0.5f*(hf[k] + hb[k]);
    __syncthreads();
    float acc = d0b[jj];
    for (int k = 0; k < UU; ++k) acc += addv[k]*d0W[k*(UU/2) + jj];
    float y = (acc - mea[jj])*rsqrtf(var[jj] + 1e-3f)*gam[jj] + bet[jj];
    y = (y > 0.f) ? y : alp[jj]*y;
    g_mid[r*(UU/2) + jj] = y;
}

// ---------------- head: dense1 + softmax ------------------------------------
__global__ void dense1_kernel(const float* __restrict__ d1W, const float* __restrict__ d1b,
                              float* __restrict__ out)
{
    int r = threadIdx.x;
    if (r >= BB) return;
    float lg[7];
    #pragma unroll
    for (int j = 0; j < 7; ++j) lg[j] = d1b[j];
    const float* mid = &g_mid[r*(UU/2)];
    for (int k = 0; k < UU/2; ++k) {
        float v = mid[k];
        #pragma unroll
        for (int j = 0; j < 7; ++j) lg[j] += v*d1W[k*7 + j];
    }
    float m = lg[0];
    #pragma unroll
    for (int j = 1; j < 7; ++j) m = fmaxf(m, lg[j]);
    float ssum = 0.f, e[7];
    #pragma unroll
    for (int j = 0; j < 7; ++j) { e[j] = expf(lg[j] - m); ssum += e[j]; }
    float inv = 1.f/ssum;
    #pragma unroll
    for (int j = 0; j < 7; ++j) out[r*7 + j] = e[j]*inv;
}

// ---------------- launch ----------------------------------------------------
extern "C" void kernel_launch(void* const* d_in, const int* in_sizes, int n_in,
                              void* d_out, int out_size)
{
    (void)in_sizes; (void)n_in; (void)out_size;
    const int*   ids = (const int*)d_in[0];
    const float* emb = (const float*)d_in[1];
    const float* Wm[2][3]; const float* Um[2][3]; const float* bm[2][3];
    for (int d = 0; d < 2; ++d)
        for (int l = 0; l < 3; ++l) {
            int base = 2 + d*9 + l*3;
            Wm[d][l] = (const float*)d_in[base];
            Um[d][l] = (const float*)d_in[base + 1];
            bm[d][l] = (const float*)d_in[base + 2];
        }
    const float* d0W = (const float*)d_in[20];
    const float* d0b = (const float*)d_in[21];
    const float* gam = (const float*)d_in[22];
    const float* bet = (const float*)d_in[23];
    const float* mea = (const float*)d_in[24];
    const float* var = (const float*)d_in[25];
    const float* alp = (const float*)d_in[26];
    const float* d1W = (const float*)d_in[27];
    const float* d1b = (const float*)d_in[28];
    float* out = (float*)d_out;

    // opt-in smem for the persistent kernel (64KB U slice + 8KB H chunk)
    cudaFuncSetAttribute(lstm_layer_kernel,
                         cudaFuncAttributeMaxDynamicSharedMemorySize, 73728);

    embed_kernel<<<(TBROWS*EMBD + 255)/256, 256>>>(ids, emb);

    for (int l = 0; l < 3; ++l) {
        dim3 gpre(GG/128, TBROWS/128, 2);
        pregemm_kernel<<<gpre, 256>>>(Wm[0][l], bm[0][l], Wm[1][l], bm[1][l], l);
        lstm_layer_kernel<<<NBLK, 128, 73728>>>(Um[0][l], Um[1][l], l);
    }

    dense0_kernel<<<BB, 256>>>(d0W, d0b, gam, bet, mea, var, alp);
    dense1_kernel<<<1, 128>>>(d1W, d1b, out);
}

// round 8
// speedup vs baseline: 1.6729x; 1.6729x over previous
#include <cuda_runtime.h>
#include <math.h>

#define TT   128      // timesteps
#define BB   128      // batch
#define EMBD 300
#define UU   512
#define GG   2048     // 4*U
#define TBROWS (TT*BB)
#define NBLK 128      // persistent blocks (<=148 SMs -> single wave, spin barrier safe)

typedef unsigned long long u64;

// packed fp32x2 helpers (sm_103a FFMA2 — only reachable via PTX)
__device__ __forceinline__ u64 pack2(float lo, float hi) {
    u64 r; asm("mov.b64 %0, {%1, %2};" : "=l"(r) : "f"(lo), "f"(hi)); return r;
}
__device__ __forceinline__ float2 unpack2(u64 v) {
    float2 f; asm("mov.b64 {%0, %1}, %2;" : "=f"(f.x), "=f"(f.y) : "l"(v)); return f;
}
__device__ __forceinline__ u64 fma2(u64 a, u64 b, u64 c) {
    u64 d; asm("fma.rn.f32x2 %0, %1, %2, %3;" : "=l"(d) : "l"(a), "l"(b), "l"(c)); return d;
}

// ---------------- scratch (static device arrays; no allocation) -------------
static __device__ float g_X[TBROWS*EMBD];                 // [t][b][e]
static __device__ float g_Zpre[2][TBROWS*GG];             // per dir: x@W + b for all (t,b)
static __device__ float g_Hseq[2][2][TBROWS*UU];          // [dir][ping][(s*B+r)*U + col]
static __device__ float g_HT[2][2][UU*BB];                // [dir][parity][col*BB + row]
static __device__ float g_mid[BB*(UU/2)];                 // dense0 output

// barrier state. MONOTONE generation: never reset (fixes exit-race deadlock).
// Between launches the counter is quiescent (stream ordering), so each launch
// reads its base at entry and waits on base+step.
static __device__ unsigned g_bar_cnt = 0;
static __device__ unsigned g_bar_gen = 0;

__device__ __forceinline__ void grid_sync(unsigned target) {
    __syncthreads();
    if (threadIdx.x == 0) {
        __threadfence();
        unsigned old = atomicAdd(&g_bar_cnt, 1);
        if (old == NBLK - 1) {
            g_bar_cnt = 0;          // ordered before gen increment below
            __threadfence();
            atomicAdd(&g_bar_gen, 1);
        } else {
            while (*(volatile unsigned*)&g_bar_gen < target) { }
        }
    }
    __syncthreads();
}

// ---------------- embedding gather ------------------------------------------
__global__ void embed_kernel(const int* __restrict__ ids, const float* __restrict__ emb) {
    int idx = blockIdx.x*256 + threadIdx.x;
    if (idx >= TBROWS*EMBD) return;
    int row = idx / EMBD;           // t*BB + b
    int e   = idx - row*EMBD;
    int t   = row >> 7;
    int b   = row & 127;
    g_X[idx] = emb[(size_t)ids[b*TT + t]*EMBD + e];
}

// ---------------- input projection: Zpre = In @ W + bias --------------------
// (R4 proven version) BM=128, BN=64, BK=16, 256 threads, 8x4 per thread.
// grid: (GG/64, TBROWS/128, 2)
__global__ void pregemm_kernel(const float* __restrict__ Wf, const float* __restrict__ bf,
                               const float* __restrict__ Wb, const float* __restrict__ bbv,
                               int layer)
{
    int d = blockIdx.z;
    const float* W    = d ? Wb  : Wf;
    const float* bias = d ? bbv : bf;
    const float* A    = (layer == 0) ? g_X : g_Hseq[d][(layer + 1) & 1];
    int K             = (layer == 0) ? EMBD : UU;
    float* Z = g_Zpre[d];

    int n0 = blockIdx.x * 64;
    int m0 = blockIdx.y * 128;
    int tid = threadIdx.x;
    int tx = tid & 15, ty = tid >> 4;

    __shared__ float As[16][132];   // padded: kills 4-way bank conflict on store
    __shared__ float Bs[16][64];
    float acc[8][4] = {};

    int nch = (K + 15) >> 4;
    for (int ch = 0; ch < nch; ++ch) {
        int k0 = ch << 4;
        // A tile: 128 rows x 16 k (K%4==0 for both 300 and 512 -> clean float4 guard)
        #pragma unroll
        for (int h = 0; h < 2; ++h) {
            int e = tid + h*256;
            int row = e >> 2, kq = (e & 3) << 2;
            float4 v = make_float4(0.f, 0.f, 0.f, 0.f);
            if (k0 + kq < K) v = *(const float4*)&A[(size_t)(m0 + row)*K + k0 + kq];
            As[kq + 0][row] = v.x; As[kq + 1][row] = v.y;
            As[kq + 2][row] = v.z; As[kq + 3][row] = v.w;
        }
        // B tile: 16 k x 64 n
        {
            int kk = tid >> 4, nq = (tid & 15) << 2;
            float4 v = make_float4(0.f, 0.f, 0.f, 0.f);
            if (k0 + kk < K) v = *(const float4*)&W[(size_t)(k0 + kk)*GG + n0 + nq];
            *(float4*)&Bs[kk][nq] = v;
        }
        __syncthreads();
        #pragma unroll
        for (int kk = 0; kk < 16; ++kk) {
            float4 a0 = *(const float4*)&As[kk][ty*8];
            float4 a1 = *(const float4*)&As[kk][ty*8 + 4];
            float4 b  = *(const float4*)&Bs[kk][tx*4];
            float av[8] = {a0.x, a0.y, a0.z, a0.w, a1.x, a1.y, a1.z, a1.w};
            float bv[4] = {b.x, b.y, b.z, b.w};
            #pragma unroll
            for (int i = 0; i < 8; ++i)
                #pragma unroll
                for (int j = 0; j < 4; ++j)
                    acc[i][j] += av[i]*bv[j];
        }
        __syncthreads();
    }
    #pragma unroll
    for (int i = 0; i < 8; ++i) {
        int m = m0 + ty*8 + i;
        int n = n0 + tx*4;
        float4 o;
        o.x = acc[i][0] + bias[n + 0];
        o.y = acc[i][1] + bias[n + 1];
        o.z = acc[i][2] + bias[n + 2];
        o.w = acc[i][3] + bias[n + 3];
        *(float4*)&Z[(size_t)m*GG + n] = o;
    }
}

// ---------------- persistent recurrent layer kernel -------------------------
// 128 blocks x 128 threads. Block: dir = bid>>6, 8 h-cols (c0 = (bid&63)*8).
// U slice resident in smem as float4{i,f,g,o} per (k, hcol). Cell state in regs.
// Inner product uses packed f32x2 FMAs: H row-pairs come free as ulonglong2
// from the shared chunk; only the 4 U broadcasts need packing (ALU pipe).
__global__ void lstm_layer_kernel(const float* __restrict__ Uf,
                                  const float* __restrict__ Ub, int layer)
{
    extern __shared__ char smem[];
    float4* Usv = (float4*)smem;              // [512][8] : k*8 + hc
    float*  Hs  = (float*)(smem + 65536);     // [16][128] : kk*128 + r

    int d   = blockIdx.x >> 6;
    int blk = blockIdx.x & 63;
    int c0  = blk << 3;
    const float* Uw = d ? Ub : Uf;
    const float* Zp = g_Zpre[d];
    int ping = layer & 1;
    float* Hseq = g_Hseq[d][ping];

    int tid = threadIdx.x;
    int tx = tid & 7;        // h-col within block
    int ty = tid >> 3;       // row-group (8 rows each)
    int j  = c0 + tx;        // global h index
    int r0 = ty << 3;

    // read barrier base BEFORE any barrier activity of this launch
    __shared__ unsigned s_base;
    if (tid == 0) s_base = *(volatile unsigned*)&g_bar_gen;

    // load U slice once (resident for all 128 steps)
    #pragma unroll 4
    for (int q = 0; q < 32; ++q) {
        int e  = q*128 + tid;
        int k  = e >> 3, hc = e & 7;
        int col = c0 + hc;
        float4 v;
        v.x = Uw[(size_t)k*GG +          col];
        v.y = Uw[(size_t)k*GG +   UU  +  col];
        v.z = Uw[(size_t)k*GG + 2*UU  +  col];
        v.w = Uw[(size_t)k*GG + 3*UU  +  col];
        Usv[k*8 + hc] = v;
    }
    __syncthreads();
    unsigned base = s_base;

    float c_reg[8];
    #pragma unroll
    for (int i = 0; i < 8; ++i) c_reg[i] = 0.f;

    unsigned bar = 0;
    for (int s = 0; s < TT; ++s) {
        // prefetch this step's Zpre rows (independent of H -> latency hides under matmul)
        int zr0 = (layer == 0 && d == 1) ? (TT - 1 - s) : s;
        float z0[8], z1[8], z2[8], z3[8];
        #pragma unroll
        for (int i = 0; i < 8; ++i) {
            const float* zp = Zp + ((size_t)zr0*BB + r0 + i)*GG + j;
            z0[i] = zp[0]; z1[i] = zp[UU]; z2[i] = zp[2*UU]; z3[i] = zp[3*UU];
        }

        u64 ac0[4], ac1[4], ac2[4], ac3[4];   // [row-pair] per gate
        #pragma unroll
        for (int p = 0; p < 4; ++p) { ac0[p] = 0ull; ac1[p] = 0ull; ac2[p] = 0ull; ac3[p] = 0ull; }

        if (s > 0) {
            const float4* HT = (const float4*)(g_HT[d][(s - 1) & 1]);
            float4 pf[4];
            #pragma unroll
            for (int q = 0; q < 4; ++q) pf[q] = __ldcg(HT + q*128 + tid);
            for (int ch = 0; ch < 32; ++ch) {
                #pragma unroll
                for (int q = 0; q < 4; ++q) ((float4*)Hs)[q*128 + tid] = pf[q];
                __syncthreads();
                if (ch < 31) {
                    const float4* src = HT + (ch + 1)*512;
                    #pragma unroll
                    for (int q = 0; q < 4; ++q) pf[q] = __ldcg(src + q*128 + tid);
                }
                #pragma unroll
                for (int kk = 0; kk < 16; ++kk) {
                    float4 u = Usv[(ch*16 + kk)*8 + tx];
                    u64 ux = pack2(u.x, u.x), uy = pack2(u.y, u.y);
                    u64 uz = pack2(u.z, u.z), uw = pack2(u.w, u.w);
                    ulonglong2 a01 = *(const ulonglong2*)&Hs[kk*128 + r0];
                    ulonglong2 a23 = *(const ulonglong2*)&Hs[kk*128 + r0 + 4];
                    u64 ap[4] = {a01.x, a01.y, a23.x, a23.y};
                    #pragma unroll
                    for (int p = 0; p < 4; ++p) {
                        ac0[p] = fma2(ap[p], ux, ac0[p]);
                        ac1[p] = fma2(ap[p], uy, ac1[p]);
                        ac2[p] = fma2(ap[p], uz, ac2[p]);
                        ac3[p] = fma2(ap[p], uw, ac3[p]);
                    }
                }
                __syncthreads();
            }
        }

        // gates + state update (thread-local)
        float hn[8];
        #pragma unroll
        for (int p = 0; p < 4; ++p) {
            float2 f0 = unpack2(ac0[p]);
            float2 f1 = unpack2(ac1[p]);
            float2 f2 = unpack2(ac2[p]);
            float2 f3 = unpack2(ac3[p]);
            float a0v[2] = {f0.x, f0.y}, a1v[2] = {f1.x, f1.y};
            float a2v[2] = {f2.x, f2.y}, a3v[2] = {f3.x, f3.y};
            #pragma unroll
            for (int e = 0; e < 2; ++e) {
                int i = 2*p + e;
                float zi = a0v[e] + z0[i];
                float zf = a1v[e] + z1[i];
                float zg = a2v[e] + z2[i];
                float zo = a3v[e] + z3[i];
                float ig = 1.f/(1.f + expf(-zi));
                float fg = 1.f/(1.f + expf(-zf));
                float sg = zg/(1.f + fabsf(zg));
                float og = 1.f/(1.f + expf(-zo));
                float cn = fg*c_reg[i] + ig*sg;
                c_reg[i] = cn;
                hn[i] = og*(cn/(1.f + fabsf(cn)));
                Hseq[((size_t)s*BB + r0 + i)*UU + j] = hn[i];
            }
        }
        float* HTc = g_HT[d][s & 1];
        *(float4*)&HTc[j*BB + r0]     = make_float4(hn[0], hn[1], hn[2], hn[3]);
        *(float4*)&HTc[j*BB + r0 + 4] = make_float4(hn[4], hn[5], hn[6], hn[7]);

        grid_sync(base + (++bar));
    }
    // NO generation reset — monotone across launches/replays (fixes exit race).
}

// ---------------- head: dense0 + BN + PReLU ---------------------------------
__global__ void dense0_kernel(const float* __restrict__ d0W, const float* __restrict__ d0b,
                              const float* __restrict__ gam, const float* __restrict__ bet,
                              const float* __restrict__ mea, const float* __restrict__ var,
                              const float* __restrict__ alp)
{
    int r = blockIdx.x;
    int jj = threadIdx.x;
    __shared__ float addv[UU];
    const float* hf = &g_Hseq[0][0][((size_t)(TT - 1)*BB + r)*UU];   // layer 2 -> ping 0
    const float* hb = &g_Hseq[1][0][((size_t)(TT - 1)*BB + r)*UU];
    for (int k = jj; k < UU; k += 256) addv[k] = 0.5f*(hf[k] + hb[k]);
    __syncthreads();
    float acc = d0b[jj];
    for (int k = 0; k < UU; ++k) acc += addv[k]*d0W[k*(UU/2) + jj];
    float y = (acc - mea[jj])*rsqrtf(var[jj] + 1e-3f)*gam[jj] + bet[jj];
    y = (y > 0.f) ? y : alp[jj]*y;
    g_mid[r*(UU/2) + jj] = y;
}

// ---------------- head: dense1 + softmax ------------------------------------
__global__ void dense1_kernel(const float* __restrict__ d1W, const float* __restrict__ d1b,
                              float* __restrict__ out)
{
    int r = threadIdx.x;
    if (r >= BB) return;
    float lg[7];
    #pragma unroll
    for (int j = 0; j < 7; ++j) lg[j] = d1b[j];
    const float* mid = &g_mid[r*(UU/2)];
    for (int k = 0; k < UU/2; ++k) {
        float v = mid[k];
        #pragma unroll
        for (int j = 0; j < 7; ++j) lg[j] += v*d1W[k*7 + j];
    }
    float m = lg[0];
    #pragma unroll
    for (int j = 1; j < 7; ++j) m = fmaxf(m, lg[j]);
    float ssum = 0.f, e[7];
    #pragma unroll
    for (int j = 0; j < 7; ++j) { e[j] = expf(lg[j] - m); ssum += e[j]; }
    float inv = 1.f/ssum;
    #pragma unroll
    for (int j = 0; j < 7; ++j) out[r*7 + j] = e[j]*inv;
}

// ---------------- launch ----------------------------------------------------
extern "C" void kernel_launch(void* const* d_in, const int* in_sizes, int n_in,
                              void* d_out, int out_size)
{
    (void)in_sizes; (void)n_in; (void)out_size;
    const int*   ids = (const int*)d_in[0];
    const float* emb = (const float*)d_in[1];
    const float* Wm[2][3]; const float* Um[2][3]; const float* bm[2][3];
    for (int d = 0; d < 2; ++d)
        for (int l = 0; l < 3; ++l) {
            int base = 2 + d*9 + l*3;
            Wm[d][l] = (const float*)d_in[base];
            Um[d][l] = (const float*)d_in[base + 1];
            bm[d][l] = (const float*)d_in[base + 2];
        }
    const float* d0W = (const float*)d_in[20];
    const float* d0b = (const float*)d_in[21];
    const float* gam = (const float*)d_in[22];
    const float* bet = (const float*)d_in[23];
    const float* mea = (const float*)d_in[24];
    const float* var = (const float*)d_in[25];
    const float* alp = (const float*)d_in[26];
    const float* d1W = (const float*)d_in[27];
    const float* d1b = (const float*)d_in[28];
    float* out = (float*)d_out;

    // opt-in smem for the persistent kernel (64KB U slice + 8KB H chunk)
    cudaFuncSetAttribute(lstm_layer_kernel,
                         cudaFuncAttributeMaxDynamicSharedMemorySize, 73728);

    embed_kernel<<<(TBROWS*EMBD + 255)/256, 256>>>(ids, emb);

    for (int l = 0; l < 3; ++l) {
        dim3 gpre(GG/64, TBROWS/128, 2);
        pregemm_kernel<<<gpre, 256>>>(Wm[0][l], bm[0][l], Wm[1][l], bm[1][l], l);
        lstm_layer_kernel<<<NBLK, 128, 73728>>>(Um[0][l], Um[1][l], l);
    }

    dense0_kernel<<<BB, 256>>>(d0W, d0b, gam, bet, mea, var, alp);
    dense1_kernel<<<1, 128>>>(d1W, d1b, out);
}

// round 9
// speedup vs baseline: 1.7226x; 1.0297x over previous
#include <cuda_runtime.h>
#include <math.h>

#define TT   128      // timesteps
#define BB   128      // batch
#define EMBD 300
#define UU   512
#define GG   2048     // 4*U
#define TBROWS (TT*BB)
#define NBLK 128      // persistent blocks (<=148 SMs -> single wave, spin barrier safe)

typedef unsigned long long u64;

// packed fp32x2 helpers (sm_103a FFMA2 — only reachable via PTX)
__device__ __forceinline__ u64 pack2(float lo, float hi) {
    u64 r; asm("mov.b64 %0, {%1, %2};" : "=l"(r) : "f"(lo), "f"(hi)); return r;
}
__device__ __forceinline__ float2 unpack2(u64 v) {
    float2 f; asm("mov.b64 {%0, %1}, %2;" : "=f"(f.x), "=f"(f.y) : "l"(v)); return f;
}
__device__ __forceinline__ u64 fma2(u64 a, u64 b, u64 c) {
    u64 d; asm("fma.rn.f32x2 %0, %1, %2, %3;" : "=l"(d) : "l"(a), "l"(b), "l"(c)); return d;
}

// ---------------- scratch (static device arrays; no allocation) -------------
static __device__ float g_X[TBROWS*EMBD];                 // [t][b][e]
static __device__ float g_Zpre[2][TBROWS*GG];             // per dir: x@W + b for all (t,b)
static __device__ float g_Hseq[2][2][TBROWS*UU];          // [dir][ping][(s*B+r)*U + col]
static __device__ float g_HT[2][2][UU*BB];                // [dir][parity][col*BB + row]
static __device__ float g_mid[BB*(UU/2)];                 // dense0 output

// barrier state. MONOTONE generation: never reset (fixes exit-race deadlock).
static __device__ unsigned g_bar_cnt = 0;
static __device__ unsigned g_bar_gen = 0;

__device__ __forceinline__ void grid_sync(unsigned target) {
    __syncthreads();
    if (threadIdx.x == 0) {
        __threadfence();
        unsigned old = atomicAdd(&g_bar_cnt, 1);
        if (old == NBLK - 1) {
            g_bar_cnt = 0;          // ordered before gen increment below
            __threadfence();
            atomicAdd(&g_bar_gen, 1);
        } else {
            while (*(volatile unsigned*)&g_bar_gen < target) { }
        }
    }
    __syncthreads();
}

// ---------------- embedding gather ------------------------------------------
__global__ void embed_kernel(const int* __restrict__ ids, const float* __restrict__ emb) {
    int idx = blockIdx.x*256 + threadIdx.x;
    if (idx >= TBROWS*EMBD) return;
    int row = idx / EMBD;           // t*BB + b
    int e   = idx - row*EMBD;
    int t   = row >> 7;
    int b   = row & 127;
    g_X[idx] = emb[(size_t)ids[b*TT + t]*EMBD + e];
}

// ---------------- input projection: Zpre = In @ W + bias --------------------
// BM=128, BN=64, BK=16, 256 threads. Same tiles as R4; inner loop uses FFMA2:
// A row-pairs free as ulonglong2 from As, B scalars broadcast-packed in regs.
// grid: (GG/64, TBROWS/128, 2)
__global__ void pregemm_kernel(const float* __restrict__ Wf, const float* __restrict__ bf,
                               const float* __restrict__ Wb, const float* __restrict__ bbv,
                               int layer)
{
    int d = blockIdx.z;
    const float* W    = d ? Wb  : Wf;
    const float* bias = d ? bbv : bf;
    const float* A    = (layer == 0) ? g_X : g_Hseq[d][(layer + 1) & 1];
    int K             = (layer == 0) ? EMBD : UU;
    float* Z = g_Zpre[d];

    int n0 = blockIdx.x * 64;
    int m0 = blockIdx.y * 128;
    int tid = threadIdx.x;
    int tx = tid & 15, ty = tid >> 4;

    __shared__ float As[16][132];   // padded; row stride 528B = 16B-multiple
    __shared__ float Bs[16][64];

    u64 acc[4][4];                  // [row-pair][col]
    #pragma unroll
    for (int p = 0; p < 4; ++p)
        #pragma unroll
        for (int j = 0; j < 4; ++j) acc[p][j] = 0ull;

    int nch = (K + 15) >> 4;
    for (int ch = 0; ch < nch; ++ch) {
        int k0 = ch << 4;
        // A tile: 128 rows x 16 k (K%4==0 for both 300 and 512 -> clean float4 guard)
        #pragma unroll
        for (int h = 0; h < 2; ++h) {
            int e = tid + h*256;
            int row = e >> 2, kq = (e & 3) << 2;
            float4 v = make_float4(0.f, 0.f, 0.f, 0.f);
            if (k0 + kq < K) v = *(const float4*)&A[(size_t)(m0 + row)*K + k0 + kq];
            As[kq + 0][row] = v.x; As[kq + 1][row] = v.y;
            As[kq + 2][row] = v.z; As[kq + 3][row] = v.w;
        }
        // B tile: 16 k x 64 n
        {
            int kk = tid >> 4, nq = (tid & 15) << 2;
            float4 v = make_float4(0.f, 0.f, 0.f, 0.f);
            if (k0 + kk < K) v = *(const float4*)&W[(size_t)(k0 + kk)*GG + n0 + nq];
            *(float4*)&Bs[kk][nq] = v;
        }
        __syncthreads();
        #pragma unroll
        for (int kk = 0; kk < 16; ++kk) {
            ulonglong2 a01 = *(const ulonglong2*)&As[kk][ty*8];
            ulonglong2 a23 = *(const ulonglong2*)&As[kk][ty*8 + 4];
            u64 ap[4] = {a01.x, a01.y, a23.x, a23.y};
            float4 b  = *(const float4*)&Bs[kk][tx*4];
            u64 bp[4] = {pack2(b.x, b.x), pack2(b.y, b.y),
                         pack2(b.z, b.z), pack2(b.w, b.w)};
            #pragma unroll
            for (int p = 0; p < 4; ++p)
                #pragma unroll
                for (int j = 0; j < 4; ++j)
                    acc[p][j] = fma2(ap[p], bp[j], acc[p][j]);
        }
        __syncthreads();
    }
    // epilogue: each acc pair holds rows (2p, 2p+1) for col j
    int n = n0 + tx*4;
    float4 bl = *(const float4*)&bias[n];
    #pragma unroll
    for (int p = 0; p < 4; ++p) {
        int m = m0 + ty*8 + 2*p;
        float2 f0 = unpack2(acc[p][0]);
        float2 f1 = unpack2(acc[p][1]);
        float2 f2 = unpack2(acc[p][2]);
        float2 f3 = unpack2(acc[p][3]);
        *(float4*)&Z[(size_t)m*GG + n] =
            make_float4(f0.x + bl.x, f1.x + bl.y, f2.x + bl.z, f3.x + bl.w);
        *(float4*)&Z[(size_t)(m + 1)*GG + n] =
            make_float4(f0.y + bl.x, f1.y + bl.y, f2.y + bl.z, f3.y + bl.w);
    }
}

// ---------------- persistent recurrent layer kernel -------------------------
// 128 blocks x 128 threads. Block: dir = bid>>6, 8 h-cols (c0 = (bid&63)*8).
// U slice resident in smem as float4{i,f,g,o} per (k, hcol). Cell state in regs.
// Inner product uses packed f32x2 FMAs (proven R8 version, unchanged).
__global__ void lstm_layer_kernel(const float* __restrict__ Uf,
                                  const float* __restrict__ Ub, int layer)
{
    extern __shared__ char smem[];
    float4* Usv = (float4*)smem;              // [512][8] : k*8 + hc
    float*  Hs  = (float*)(smem + 65536);     // [16][128] : kk*128 + r

    int d   = blockIdx.x >> 6;
    int blk = blockIdx.x & 63;
    int c0  = blk << 3;
    const float* Uw = d ? Ub : Uf;
    const float* Zp = g_Zpre[d];
    int ping = layer & 1;
    float* Hseq = g_Hseq[d][ping];

    int tid = threadIdx.x;
    int tx = tid & 7;        // h-col within block
    int ty = tid >> 3;       // row-group (8 rows each)
    int j  = c0 + tx;        // global h index
    int r0 = ty << 3;

    // read barrier base BEFORE any barrier activity of this launch
    __shared__ unsigned s_base;
    if (tid == 0) s_base = *(volatile unsigned*)&g_bar_gen;

    // load U slice once (resident for all 128 steps)
    #pragma unroll 4
    for (int q = 0; q < 32; ++q) {
        int e  = q*128 + tid;
        int k  = e >> 3, hc = e & 7;
        int col = c0 + hc;
        float4 v;
        v.x = Uw[(size_t)k*GG +          col];
        v.y = Uw[(size_t)k*GG +   UU  +  col];
        v.z = Uw[(size_t)k*GG + 2*UU  +  col];
        v.w = Uw[(size_t)k*GG + 3*UU  +  col];
        Usv[k*8 + hc] = v;
    }
    __syncthreads();
    unsigned base = s_base;

    float c_reg[8];
    #pragma unroll
    for (int i = 0; i < 8; ++i) c_reg[i] = 0.f;

    unsigned bar = 0;
    for (int s = 0; s < TT; ++s) {
        // prefetch this step's Zpre rows (independent of H -> latency hides under matmul)
        int zr0 = (layer == 0 && d == 1) ? (TT - 1 - s) : s;
        float z0[8], z1[8], z2[8], z3[8];
        #pragma unroll
        for (int i = 0; i < 8; ++i) {
            const float* zp = Zp + ((size_t)zr0*BB + r0 + i)*GG + j;
            z0[i] = zp[0]; z1[i] = zp[UU]; z2[i] = zp[2*UU]; z3[i] = zp[3*UU];
        }

        u64 ac0[4], ac1[4], ac2[4], ac3[4];   // [row-pair] per gate
        #pragma unroll
        for (int p = 0; p < 4; ++p) { ac0[p] = 0ull; ac1[p] = 0ull; ac2[p] = 0ull; ac3[p] = 0ull; }

        if (s > 0) {
            const float4* HT = (const float4*)(g_HT[d][(s - 1) & 1]);
            float4 pf[4];
            #pragma unroll
            for (int q = 0; q < 4; ++q) pf[q] = __ldcg(HT + q*128 + tid);
            for (int ch = 0; ch < 32; ++ch) {
                #pragma unroll
                for (int q = 0; q < 4; ++q) ((float4*)Hs)[q*128 + tid] = pf[q];
                __syncthreads();
                if (ch < 31) {
                    const float4* src = HT + (ch + 1)*512;
                    #pragma unroll
                    for (int q = 0; q < 4; ++q) pf[q] = __ldcg(src + q*128 + tid);
                }
                #pragma unroll
                for (int kk = 0; kk < 16; ++kk) {
                    float4 u = Usv[(ch*16 + kk)*8 + tx];
                    u64 ux = pack2(u.x, u.x), uy = pack2(u.y, u.y);
                    u64 uz = pack2(u.z, u.z), uw = pack2(u.w, u.w);
                    ulonglong2 a01 = *(const ulonglong2*)&Hs[kk*128 + r0];
                    ulonglong2 a23 = *(const ulonglong2*)&Hs[kk*128 + r0 + 4];
                    u64 ap[4] = {a01.x, a01.y, a23.x, a23.y};
                    #pragma unroll
                    for (int p = 0; p < 4; ++p) {
                        ac0[p] = fma2(ap[p], ux, ac0[p]);
                        ac1[p] = fma2(ap[p], uy, ac1[p]);
                        ac2[p] = fma2(ap[p], uz, ac2[p]);
                        ac3[p] = fma2(ap[p], uw, ac3[p]);
                    }
                }
                __syncthreads();
            }
        }

        // gates + state update (thread-local)
        float hn[8];
        #pragma unroll
        for (int p = 0; p < 4; ++p) {
            float2 f0 = unpack2(ac0[p]);
            float2 f1 = unpack2(ac1[p]);
            float2 f2 = unpack2(ac2[p]);
            float2 f3 = unpack2(ac3[p]);
            float a0v[2] = {f0.x, f0.y}, a1v[2] = {f1.x, f1.y};
            float a2v[2] = {f2.x, f2.y}, a3v[2] = {f3.x, f3.y};
            #pragma unroll
            for (int e = 0; e < 2; ++e) {
                int i = 2*p + e;
                float zi = a0v[e] + z0[i];
                float zf = a1v[e] + z1[i];
                float zg = a2v[e] + z2[i];
                float zo = a3v[e] + z3[i];
                float ig = 1.f/(1.f + expf(-zi));
                float fg = 1.f/(1.f + expf(-zf));
                float sg = zg/(1.f + fabsf(zg));
                float og = 1.f/(1.f + expf(-zo));
                float cn = fg*c_reg[i] + ig*sg;
                c_reg[i] = cn;
                hn[i] = og*(cn/(1.f + fabsf(cn)));
                Hseq[((size_t)s*BB + r0 + i)*UU + j] = hn[i];
            }
        }
        float* HTc = g_HT[d][s & 1];
        *(float4*)&HTc[j*BB + r0]     = make_float4(hn[0], hn[1], hn[2], hn[3]);
        *(float4*)&HTc[j*BB + r0 + 4] = make_float4(hn[4], hn[5], hn[6], hn[7]);

        grid_sync(base + (++bar));
    }
    // NO generation reset — monotone across launches/replays.
}

// ---------------- head: dense0 + BN + PReLU ---------------------------------
__global__ void dense0_kernel(const float* __restrict__ d0W, const float* __restrict__ d0b,
                              const float* __restrict__ gam, const float* __restrict__ bet,
                              const float* __restrict__ mea, const float* __restrict__ var,
                              const float* __restrict__ alp)
{
    int r = blockIdx.x;
    int jj = threadIdx.x;
    __shared__ float addv[UU];
    const float* hf = &g_Hseq[0][0][((size_t)(TT - 1)*BB + r)*UU];   // layer 2 -> ping 0
    const float* hb = &g_Hseq[1][0][((size_t)(TT - 1)*BB + r)*UU];
    for (int k = jj; k < UU; k += 256) addv[k] = 0.5f*(hf[k] + hb[k]);
    __syncthreads();
    float acc = d0b[jj];
    for (int k = 0; k < UU; ++k) acc += addv[k]*d0W[k*(UU/2) + jj];
    float y = (acc - mea[jj])*rsqrtf(var[jj] + 1e-3f)*gam[jj] + bet[jj];
    y = (y > 0.f) ? y : alp[jj]*y;
    g_mid[r*(UU/2) + jj] = y;
}

// ---------------- head: dense1 + softmax ------------------------------------
__global__ void dense1_kernel(const float* __restrict__ d1W, const float* __restrict__ d1b,
                              float* __restrict__ out)
{
    int r = threadIdx.x;
    if (r >= BB) return;
    float lg[7];
    #pragma unroll
    for (int j = 0; j < 7; ++j) lg[j] = d1b[j];
    const float* mid = &g_mid[r*(UU/2)];
    for (int k = 0; k < UU/2; ++k) {
        float v = mid[k];
        #pragma unroll
        for (int j = 0; j < 7; ++j) lg[j] += v*d1W[k*7 + j];
    }
    float m = lg[0];
    #pragma unroll
    for (int j = 1; j < 7; ++j) m = fmaxf(m, lg[j]);
    float ssum = 0.f, e[7];
    #pragma unroll
    for (int j = 0; j < 7; ++j) { e[j] = expf(lg[j] - m); ssum += e[j]; }
    float inv = 1.f/ssum;
    #pragma unroll
    for (int j = 0; j < 7; ++j) out[r*7 + j] = e[j]*inv;
}

// ---------------- launch ----------------------------------------------------
extern "C" void kernel_launch(void* const* d_in, const int* in_sizes, int n_in,
                              void* d_out, int out_size)
{
    (void)in_sizes; (void)n_in; (void)out_size;
    const int*   ids = (const int*)d_in[0];
    const float* emb = (const float*)d_in[1];
    const float* Wm[2][3]; const float* Um[2][3]; const float* bm[2][3];
    for (int d = 0; d < 2; ++d)
        for (int l = 0; l < 3; ++l) {
            int base = 2 + d*9 + l*3;
            Wm[d][l] = (const float*)d_in[base];
            Um[d][l] = (const float*)d_in[base + 1];
            bm[d][l] = (const float*)d_in[base + 2];
        }
    const float* d0W = (const float*)d_in[20];
    const float* d0b = (const float*)d_in[21];
    const float* gam = (const float*)d_in[22];
    const float* bet = (const float*)d_in[23];
    const float* mea = (const float*)d_in[24];
    const float* var = (const float*)d_in[25];
    const float* alp = (const float*)d_in[26];
    const float* d1W = (const float*)d_in[27];
    const float* d1b = (const float*)d_in[28];
    float* out = (float*)d_out;

    // opt-in smem for the persistent kernel (64KB U slice + 8KB H chunk)
    cudaFuncSetAttribute(lstm_layer_kernel,
                         cudaFuncAttributeMaxDynamicSharedMemorySize, 73728);

    embed_kernel<<<(TBROWS*EMBD + 255)/256, 256>>>(ids, emb);

    for (int l = 0; l < 3; ++l) {
        dim3 gpre(GG/64, TBROWS/128, 2);
        pregemm_kernel<<<gpre, 256>>>(Wm[0][l], bm[0][l], Wm[1][l], bm[1][l], l);
        lstm_layer_kernel<<<NBLK, 128, 73728>>>(Um[0][l], Um[1][l], l);
    }

    dense0_kernel<<<BB, 256>>>(d0W, d0b, gam, bet, mea, var, alp);
    dense1_kernel<<<1, 128>>>(d1W, d1b, out);
}

// round 12
// speedup vs baseline: 1.8306x; 1.0627x over previous
#include <cuda_runtime.h>
#include <cuda_bf16.h>
#include <math.h>
#include <stdint.h>

#define TT   128      // timesteps
#define BB   128      // batch
#define EMBD 300
#define UU   512
#define GG   2048     // 4*U
#define TBROWS (TT*BB)
#define NBLK 128      // persistent blocks (<=148 SMs -> single wave, spin barrier safe)
#define KMAX2 1536    // max stacked K' (3*512)

typedef unsigned long long u64;

// ---------------- packed fp32x2 helpers (FFMA2) ------------------------------
__device__ __forceinline__ u64 pack2(float lo, float hi) {
    u64 r; asm("mov.b64 %0, {%1, %2};" : "=l"(r) : "f"(lo), "f"(hi)); return r;
}
__device__ __forceinline__ float2 unpack2(u64 v) {
    float2 f; asm("mov.b64 {%0, %1}, %2;" : "=f"(f.x), "=f"(f.y) : "l"(v)); return f;
}
__device__ __forceinline__ u64 fma2(u64 a, u64 b, u64 c) {
    u64 d; asm("fma.rn.f32x2 %0, %1, %2, %3;" : "=l"(d) : "l"(a), "l"(b), "l"(c)); return d;
}

__device__ __forceinline__ uint32_t smem_u32(const void* p) {
    uint32_t a;
    asm("{ .reg .u64 t; cvta.to.shared.u64 t, %1; cvt.u32.u64 %0, t; }" : "=r"(a) : "l"(p));
    return a;
}

// ---------------- scratch (static device arrays; no allocation) -------------
static __device__ float g_X[TBROWS*EMBD];                 // [t][b][e]
static __device__ float g_Zpre[2][TBROWS*GG];             // per dir: x@W + b for all (t,b)
static __device__ float g_Hseq[2][2][TBROWS*UU];          // [dir][ping][(s*B+r)*U + col]
static __device__ float g_HT[2][2][UU*BB];                // [dir][parity][col*BB + row]
static __device__ float g_mid[BB*(UU/2)];                 // dense0 output
static __device__ __nv_bfloat16 g_A2[2][(size_t)TBROWS*KMAX2];  // stacked [A_hi|A_hi|A_lo]
static __device__ __nv_bfloat16 g_W2T[2][(size_t)GG*KMAX2];     // [n][k'] stacked [W_hi|W_lo|W_hi]

// barrier state. MONOTONE generation: never reset (fixes exit-race deadlock).
static __device__ unsigned g_bar_cnt = 0;
static __device__ unsigned g_bar_gen = 0;

__device__ __forceinline__ void grid_sync(unsigned target) {
    __syncthreads();
    if (threadIdx.x == 0) {
        __threadfence();
        unsigned old = atomicAdd(&g_bar_cnt, 1);
        if (old == NBLK - 1) {
            g_bar_cnt = 0;          // ordered before gen increment below
            __threadfence();
            atomicAdd(&g_bar_gen, 1);
        } else {
            while (*(volatile unsigned*)&g_bar_gen < target) { }
        }
    }
    __syncthreads();
}

// ---------------- embedding gather ------------------------------------------
__global__ void embed_kernel(const int* __restrict__ ids, const float* __restrict__ emb) {
    int idx = blockIdx.x*256 + threadIdx.x;
    if (idx >= TBROWS*EMBD) return;
    int row = idx / EMBD;           // t*BB + b
    int e   = idx - row*EMBD;
    int t   = row >> 7;
    int b   = row & 127;
    g_X[idx] = emb[(size_t)ids[b*TT + t]*EMBD + e];
}

// ---------------- bf16 split conversions -------------------------------------
// W2T[dir][n][k'] : sections [W_hi | W_lo | W_hi], zero-padded k in [K,S)
__global__ void convW_kernel(const float* __restrict__ Wf, const float* __restrict__ Wb,
                             int S, int K2, int K)
{
    int gid = blockIdx.x*256 + threadIdx.x;               // total = 2*S*GG
    int n   = gid & (GG - 1);
    int rest = gid >> 11;
    int kh  = rest % S;
    int dir = rest / S;
    const float* W = dir ? Wb : Wf;
    float v = (kh < K) ? W[(size_t)kh*GG + n] : 0.f;
    __nv_bfloat16 hi = __float2bfloat16(v);
    __nv_bfloat16 lo = __float2bfloat16(v - __bfloat162float(hi));
    __nv_bfloat16* dst = &g_W2T[dir][(size_t)n*K2 + kh];
    dst[0]     = hi;
    dst[S]     = lo;
    dst[2*S]   = hi;
}

// A2[dir][m][k'] : sections [A_hi | A_hi | A_lo], zero-padded
__global__ void convA_kernel(int layer, int S, int K2)
{
    int gid = blockIdx.x*256 + threadIdx.x;               // total = 2*TBROWS*S
    int kh  = gid % S;
    int rest = gid / S;
    int m   = rest & (TBROWS - 1);
    int dir = rest >> 14;
    float v;
    if (layer == 0) v = (kh < EMBD) ? g_X[(size_t)m*EMBD + kh] : 0.f;
    else            v = g_Hseq[dir][(layer + 1) & 1][(size_t)m*UU + kh];
    __nv_bfloat16 hi = __float2bfloat16(v);
    __nv_bfloat16 lo = __float2bfloat16(v - __bfloat162float(hi));
    __nv_bfloat16* dst = &g_A2[dir][(size_t)m*K2 + kh];
    dst[0]     = hi;
    dst[S]     = hi;
    dst[2*S]   = lo;
}

// ---------------- tensor-core input projection (mma.sync bf16) ---------------
// Zpre[m,n] = A2[m,:] @ W2T[n,:] + bias[n], fp32 accumulate.
// Block: 128M x 64N, 256 threads (8 warps, warp = 32x32). BK=32.
// grid: (GG/64, TBROWS/128, 2)
#define APITCH 40   // bf16 elems per smem row (80B pitch -> conflict-free ldmatrix)
__global__ void pregemm_mma_kernel(const float* __restrict__ bf_,
                                   const float* __restrict__ bb_, int K2)
{
    __shared__ __align__(16) __nv_bfloat16 As[128*APITCH];
    __shared__ __align__(16) __nv_bfloat16 Bs[64*APITCH];

    int d  = blockIdx.z;
    int n0 = blockIdx.x * 64;
    int m0 = blockIdx.y * 128;
    const __nv_bfloat16* A2 = g_A2[d];
    const __nv_bfloat16* BT = g_W2T[d];
    const float* bias = d ? bb_ : bf_;
    float* Z = g_Zpre[d];

    int tid  = threadIdx.x;
    int wid  = tid >> 5;
    int lane = tid & 31;
    int warp_m = wid >> 1;          // 0..3 -> 32 M rows each
    int warp_n = wid & 1;           // 0..1 -> 32 N cols each

    uint32_t uA = smem_u32(As);
    uint32_t uB = smem_u32(Bs);

    float acc[2][4][4];             // [m16 tile][n8 tile][frag]
    #pragma unroll
    for (int i = 0; i < 2; ++i)
        #pragma unroll
        for (int j = 0; j < 4; ++j)
            #pragma unroll
            for (int q = 0; q < 4; ++q) acc[i][j][q] = 0.f;

    // ldmatrix source addresses (fixed per thread, advance by k-step)
    uint32_t aAddrBase = uA + ((warp_m*32 + (lane & 15))*APITCH + (lane >> 4)*8)*2;
    uint32_t bAddrBase = uB + ((warp_n*32 + (lane & 7) + ((lane >> 4) & 1)*8)*APITCH
                               + ((lane >> 3) & 1)*8)*2;

    int nch = K2 >> 5;
    for (int ch = 0; ch < nch; ++ch) {
        // stage A chunk: 128 rows x 32 k  (512 uint4, 2 per thread)
        #pragma unroll
        for (int h = 0; h < 2; ++h) {
            int e = tid + h*256;
            int row = e >> 2, c16 = e & 3;
            uint4 v = __ldg((const uint4*)(A2 + (size_t)(m0 + row)*K2 + ch*32) + c16);
            *(uint4*)&As[row*APITCH + c16*8] = v;
        }
        // stage B chunk: 64 rows x 32 k (256 uint4, 1 per thread)
        {
            int row = tid >> 2, c16 = tid & 3;
            uint4 v = __ldg((const uint4*)(BT + (size_t)(n0 + row)*K2 + ch*32) + c16);
            *(uint4*)&Bs[row*APITCH + c16*8] = v;
        }
        __syncthreads();

        #pragma unroll
        for (int ks = 0; ks < 2; ++ks) {
            // A frags: two m16 tiles
            uint32_t a[2][4];
            #pragma unroll
            for (int mt = 0; mt < 2; ++mt) {
                uint32_t addr = aAddrBase + (mt*16*APITCH + ks*16)*2;
                asm volatile("ldmatrix.sync.aligned.m8n8.x4.shared.b16 {%0,%1,%2,%3}, [%4];"
                             : "=r"(a[mt][0]), "=r"(a[mt][1]), "=r"(a[mt][2]), "=r"(a[mt][3])
                             : "r"(addr));
            }
            // B frags: four n8 tiles (two x4 loads of 16 n each)
            uint32_t b[4][2];
            #pragma unroll
            for (int nt2 = 0; nt2 < 2; ++nt2) {
                uint32_t addr = bAddrBase + (nt2*16*APITCH + ks*16)*2;
                uint32_t q0, q1, q2, q3;
                asm volatile("ldmatrix.sync.aligned.m8n8.x4.shared.b16 {%0,%1,%2,%3}, [%4];"
                             : "=r"(q0), "=r"(q1), "=r"(q2), "=r"(q3) : "r"(addr));
                b[nt2*2 + 0][0] = q0; b[nt2*2 + 0][1] = q1;
                b[nt2*2 + 1][0] = q2; b[nt2*2 + 1][1] = q3;
            }
            #pragma unroll
            for (int mt = 0; mt < 2; ++mt)
                #pragma unroll
                for (int nt = 0; nt < 4; ++nt) {
                    asm volatile(
                        "mma.sync.aligned.m16n8k16.row.col.f32.bf16.bf16.f32 "
                        "{%0,%1,%2,%3}, {%4,%5,%6,%7}, {%8,%9}, {%0,%1,%2,%3};"
                        : "+f"(acc[mt][nt][0]), "+f"(acc[mt][nt][1]),
                          "+f"(acc[mt][nt][2]), "+f"(acc[mt][nt][3])
                        : "r"(a[mt][0]), "r"(a[mt][1]), "r"(a[mt][2]), "r"(a[mt][3]),
                          "r"(b[nt][0]), "r"(b[nt][1]));
                }
        }
        __syncthreads();
    }

    // epilogue: C frag m16n8 -> thread holds (row=lane>>2, col=2*(lane&3)) and row+8
    #pragma unroll
    for (int mt = 0; mt < 2; ++mt) {
        #pragma unroll
        for (int nt = 0; nt < 4; ++nt) {
            int mg = m0 + warp_m*32 + mt*16 + (lane >> 2);
            int ng = n0 + warp_n*32 + nt*8 + 2*(lane & 3);
            float2 bl = *(const float2*)&bias[ng];
            float2 o0 = make_float2(acc[mt][nt][0] + bl.x, acc[mt][nt][1] + bl.y);
            float2 o1 = make_float2(acc[mt][nt][2] + bl.x, acc[mt][nt][3] + bl.y);
            *(float2*)&Z[(size_t)mg*GG + ng]       = o0;
            *(float2*)&Z[(size_t)(mg + 8)*GG + ng] = o1;
        }
    }
}

// ---------------- persistent recurrent layer kernel (R8/R9 proven) ----------
__global__ void lstm_layer_kernel(const float* __restrict__ Uf,
                                  const float* __restrict__ Ub, int layer)
{
    extern __shared__ char smem[];
    float4* Usv = (float4*)smem;              // [512][8] : k*8 + hc
    float*  Hs  = (float*)(smem + 65536);     // [16][128] : kk*128 + r

    int d   = blockIdx.x >> 6;
    int blk = blockIdx.x & 63;
    int c0  = blk << 3;
    const float* Uw = d ? Ub : Uf;
    const float* Zp = g_Zpre[d];
    int ping = layer & 1;
    float* Hseq = g_Hseq[d][ping];

    int tid = threadIdx.x;
    int tx = tid & 7;
    int ty = tid >> 3;
    int j  = c0 + tx;
    int r0 = ty << 3;

    __shared__ unsigned s_base;
    if (tid == 0) s_base = *(volatile unsigned*)&g_bar_gen;

    #pragma unroll 4
    for (int q = 0; q < 32; ++q) {
        int e  = q*128 + tid;
        int k  = e >> 3, hc = e & 7;
        int col = c0 + hc;
        float4 v;
        v.x = Uw[(size_t)k*GG +          col];
        v.y = Uw[(size_t)k*GG +   UU  +  col];
        v.z = Uw[(size_t)k*GG + 2*UU  +  col];
        v.w = Uw[(size_t)k*GG + 3*UU  +  col];
        Usv[k*8 + hc] = v;
    }
    __syncthreads();
    unsigned base = s_base;

    float c_reg[8];
    #pragma unroll
    for (int i = 0; i < 8; ++i) c_reg[i] = 0.f;

    unsigned bar = 0;
    for (int s = 0; s < TT; ++s) {
        int zr0 = (layer == 0 && d == 1) ? (TT - 1 - s) : s;
        float z0[8], z1[8], z2[8], z3[8];
        #pragma unroll
        for (int i = 0; i < 8; ++i) {
            const float* zp = Zp + ((size_t)zr0*BB + r0 + i)*GG + j;
            z0[i] = zp[0]; z1[i] = zp[UU]; z2[i] = zp[2*UU]; z3[i] = zp[3*UU];
        }

        u64 ac0[4], ac1[4], ac2[4], ac3[4];
        #pragma unroll
        for (int p = 0; p < 4; ++p) { ac0[p] = 0ull; ac1[p] = 0ull; ac2[p] = 0ull; ac3[p] = 0ull; }

        if (s > 0) {
            const float4* HT = (const float4*)(g_HT[d][(s - 1) & 1]);
            float4 pf[4];
            #pragma unroll
            for (int q = 0; q < 4; ++q) pf[q] = __ldcg(HT + q*128 + tid);
            for (int ch = 0; ch < 32; ++ch) {
                #pragma unroll
                for (int q = 0; q < 4; ++q) ((float4*)Hs)[q*128 + tid] = pf[q];
                __syncthreads();
                if (ch < 31) {
                    const float4* src = HT + (ch + 1)*512;
                    #pragma unroll
                    for (int q = 0; q < 4; ++q) pf[q] = __ldcg(src + q*128 + tid);
                }
                #pragma unroll
                for (int kk = 0; kk < 16; ++kk) {
                    float4 u = Usv[(ch*16 + kk)*8 + tx];
                    u64 ux = pack2(u.x, u.x), uy = pack2(u.y, u.y);
                    u64 uz = pack2(u.z, u.z), uw = pack2(u.w, u.w);
                    ulonglong2 a01 = *(const ulonglong2*)&Hs[kk*128 + r0];
                    ulonglong2 a23 = *(const ulonglong2*)&Hs[kk*128 + r0 + 4];
                    u64 ap[4] = {a01.x, a01.y, a23.x, a23.y};
                    #pragma unroll
                    for (int p = 0; p < 4; ++p) {
                        ac0[p] = fma2(ap[p], ux, ac0[p]);
                        ac1[p] = fma2(ap[p], uy, ac1[p]);
                        ac2[p] = fma2(ap[p], uz, ac2[p]);
                        ac3[p] = fma2(ap[p], uw, ac3[p]);
                    }
                }
                __syncthreads();
            }
        }

        float hn[8];
        #pragma unroll
        for (int p = 0; p < 4; ++p) {
            float2 f0 = unpack2(ac0[p]);
            float2 f1 = unpack2(ac1[p]);
            float2 f2 = unpack2(ac2[p]);
            float2 f3 = unpack2(ac3[p]);
            float a0v[2] = {f0.x, f0.y}, a1v[2] = {f1.x, f1.y};
            float a2v[2] = {f2.x, f2.y}, a3v[2] = {f3.x, f3.y};
            #pragma unroll
            for (int e = 0; e < 2; ++e) {
                int i = 2*p + e;
                float zi = a0v[e] + z0[i];
                float zf = a1v[e] + z1[i];
                float zg = a2v[e] + z2[i];
                float zo = a3v[e] + z3[i];
                float ig = 1.f/(1.f + expf(-zi));
                float fg = 1.f/(1.f + expf(-zf));
                float sg = zg/(1.f + fabsf(zg));
                float og = 1.f/(1.f + expf(-zo));
                float cn = fg*c_reg[i] + ig*sg;
                c_reg[i] = cn;
                hn[i] = og*(cn/(1.f + fabsf(cn)));
                Hseq[((size_t)s*BB + r0 + i)*UU + j] = hn[i];
            }
        }
        float* HTc = g_HT[d][s & 1];
        *(float4*)&HTc[j*BB + r0]     = make_float4(hn[0], hn[1], hn[2], hn[3]);
        *(float4*)&HTc[j*BB + r0 + 4] = make_float4(hn[4], hn[5], hn[6], hn[7]);

        grid_sync(base + (++bar));
    }
}

// ---------------- head: dense0 + BN + PReLU ---------------------------------
__global__ void dense0_kernel(const float* __restrict__ d0W, const float* __restrict__ d0b,
                              const float* __restrict__ gam, const float* __restrict__ bet,
                              const float* __restrict__ mea, const float* __restrict__ var,
                              const float* __restrict__ alp)
{
    int r = blockIdx.x;
    int jj = threadIdx.x;
    __shared__ float addv[UU];
    const float* hf = &g_Hseq[0][0][((size_t)(TT - 1)*BB + r)*UU];   // layer 2 -> ping 0
    const float* hb = &g_Hseq[1][0][((size_t)(TT - 1)*BB + r)*UU];
    for (int k = jj; k < UU; k += 256) addv[k] = 0.5f*(hf[k] + hb[k]);
    __syncthreads();
    float acc = d0b[jj];
    for (int k = 0; k < UU; ++k) acc += addv[k]*d0W[k*(UU/2) + jj];
    float y = (acc - mea[jj])*rsqrtf(var[jj] + 1e-3f)*gam[jj] + bet[jj];
    y = (y > 0.f) ? y : alp[jj]*y;
    g_mid[r*(UU/2) + jj] = y;
}

// ---------------- head: dense1 + softmax ------------------------------------
__global__ void dense1_kernel(const float* __restrict__ d1W, const float* __restrict__ d1b,
                              float* __restrict__ out)
{
    int r = threadIdx.x;
    if (r >= BB) return;
    float lg[7];
    #pragma unroll
    for (int j = 0; j < 7; ++j) lg[j] = d1b[j];
    const float* mid = &g_mid[r*(UU/2)];
    for (int k = 0; k < UU/2; ++k) {
        float v = mid[k];
        #pragma unroll
        for (int j = 0; j < 7; ++j) lg[j] += v*d1W[k*7 + j];
    }
    float m = lg[0];
    #pragma unroll
    for (int j = 1; j < 7; ++j) m = fmaxf(m, lg[j]);
    float ssum = 0.f, e[7];
    #pragma unroll
    for (int j = 0; j < 7; ++j) { e[j] = expf(lg[j] - m); ssum += e[j]; }
    float inv = 1.f/ssum;
    #pragma unroll
    for (int j = 0; j < 7; ++j) out[r*7 + j] = e[j]*inv;
}

// ---------------- launch ----------------------------------------------------
extern "C" void kernel_launch(void* const* d_in, const int* in_sizes, int n_in,
                              void* d_out, int out_size)
{
    (void)in_sizes; (void)n_in; (void)out_size;
    const int*   ids = (const int*)d_in[0];
    const float* emb = (const float*)d_in[1];
    const float* Wm[2][3]; const float* Um[2][3]; const float* bm[2][3];
    for (int d = 0; d < 2; ++d)
        for (int l = 0; l < 3; ++l) {
            int base = 2 + d*9 + l*3;
            Wm[d][l] = (const float*)d_in[base];
            Um[d][l] = (const float*)d_in[base + 1];
            bm[d][l] = (const float*)d_in[base + 2];
        }
    const float* d0W = (const float*)d_in[20];
    const float* d0b = (const float*)d_in[21];
    const float* gam = (const float*)d_in[22];
    const float* bet = (const float*)d_in[23];
    const float* mea = (const float*)d_in[24];
    const float* var = (const float*)d_in[25];
    const float* alp = (const float*)d_in[26];
    const float* d1W = (const float*)d_in[27];
    const float* d1b = (const float*)d_in[28];
    float* out = (float*)d_out;

    cudaFuncSetAttribute(lstm_layer_kernel,
                         cudaFuncAttributeMaxDynamicSharedMemorySize, 73728);

    embed_kernel<<<(TBROWS*EMBD + 255)/256, 256>>>(ids, emb);

    for (int l = 0; l < 3; ++l) {
        int K  = (l == 0) ? EMBD : UU;     // logical K
        int S  = (l == 0) ? 320  : 512;    // padded section size (multiple of 64)
        int K2 = 3*S;                      // stacked K'
        convW_kernel<<<(2*S*GG)/256, 256>>>(Wm[0][l], Wm[1][l], S, K2, K);
        convA_kernel<<<(2*TBROWS*S)/256, 256>>>(l, S, K2);
        dim3 gmm(GG/64, TBROWS/128, 2);
        pregemm_mma_kernel<<<gmm, 256>>>(bm[0][l], bm[1][l], K2);
        lstm_layer_kernel<<<NBLK, 128, 73728>>>(Um[0][l], Um[1][l], l);
    }

    dense0_kernel<<<BB, 256>>>(d0W, d0b, gam, bet, mea, var, alp);
    dense1_kernel<<<1, 128>>>(d1W, d1b, out);
}